// round 15
// baseline (speedup 1.0000x reference)
#include <cuda_runtime.h>
#include <cuda_fp16.h>
#include <cstdint>

// ---------------------------------------------------------------------------
// Problem constants
// ---------------------------------------------------------------------------
#define NB    8
#define CINCH 512
#define COUTC 512
#define ZDIM  512
#define M_TOT (NB * 64 * 64)        // 32768 pixels
#define P_TILES 8192                // 8 images * 32*32 Winograd tiles (2x2 out)

#define DENSE_COEF (0.0625f)        // sqrt(2/512)
#define CONV_COEF  (1.0f / 48.0f)   // sqrt(2/4608)
#define CONV_COEF2 (1.0f / 2304.0f)

// Winograd-domain GEMM tiling: per pos, [8192 x 512] * [512 x 512]
#define BM 128
#define BN 128
#define BK 64
#define NSTG 8                      // 512 / 64 k-stages per tile
#define STAGES 3
#define NTILES_G (16 * (P_TILES / BM) * (COUTC / BN))   // 4096
#define GRID_P 304                  // persistent CTAs (2 per SM)

// smem rows: 64 halves (128B data) padded to 144B -> conflict-free ldmatrix
#define ROWB 144
#define A_ST_BYTES (BM * ROWB)      // 18432
#define B_ST_BYTES (BN * ROWB)      // 18432
#define STAGE_BYTES (A_ST_BYTES + B_ST_BYTES)   // 36864
#define SMEM_TOTAL (STAGES * STAGE_BYTES)       // 110592

// ---------------------------------------------------------------------------
// Scratch (device globals; no runtime allocation allowed)
// ---------------------------------------------------------------------------
__device__ float  g_s[NB * CINCH];
__device__ float  g_d[NB * COUTC];
__device__ float  g_w2[CINCH * COUTC];
__device__ __half g_V[16 * P_TILES * CINCH];    // input transform  [pos][p][cin]
__device__ __half g_U[16 * CINCH * COUTC];      // weight transform [pos][cout][cin]
__device__ __half g_M[16 * P_TILES * COUTC];    // GEMM out fp16    [pos][p][cout]
__device__ int    g_ctr;                        // persistent tile queue

// ---------------------------------------------------------------------------
// Helpers
// ---------------------------------------------------------------------------
__device__ __forceinline__ uint32_t smem_u32(const void* p) {
    uint32_t a;
    asm("{ .reg .u64 t; cvta.to.shared.u64 t, %1; cvt.u32.u64 %0, t; }" : "=r"(a) : "l"(p));
    return a;
}

__device__ __forceinline__ void cpa16(uint32_t dst, const void* src) {
    asm volatile("cp.async.cg.shared.global.L2::128B [%0], [%1], 16;"
                 :: "r"(dst), "l"(src) : "memory");
}

#define CP_COMMIT() asm volatile("cp.async.commit_group;" ::: "memory")
#define CP_WAIT1()  asm volatile("cp.async.wait_group 1;" ::: "memory")
#define CP_WAIT0()  asm volatile("cp.async.wait_group 0;" ::: "memory")

#define LDMX4(r, addr)                                                        \
    asm volatile("ldmatrix.sync.aligned.m8n8.x4.shared.b16 {%0,%1,%2,%3}, [%4];" \
                 : "=r"((r)[0]), "=r"((r)[1]), "=r"((r)[2]), "=r"((r)[3])     \
                 : "r"(addr))

#define MMA_F16(d, a, b0, b1)                                                 \
    asm volatile(                                                             \
        "mma.sync.aligned.m16n8k16.row.col.f32.f16.f16.f32 "                  \
        "{%0,%1,%2,%3}, {%4,%5,%6,%7}, {%8,%9}, {%0,%1,%2,%3};"               \
        : "+f"((d)[0]), "+f"((d)[1]), "+f"((d)[2]), "+f"((d)[3])              \
        : "r"((a)[0]), "r"((a)[1]), "r"((a)[2]), "r"((a)[3]),                 \
          "r"(b0), "r"(b1))

// ---------------------------------------------------------------------------
// Prologue: style vector (+ queue reset), w2, demod  (R9 exact)
// ---------------------------------------------------------------------------
__global__ void k_style(const float* __restrict__ latent,
                        const float* __restrict__ dense_w,
                        const float* __restrict__ dense_b) {
    if (blockIdx.x == 0 && threadIdx.x == 0) g_ctr = 0;   // reset tile queue
    const int n = blockIdx.x;
    const int c = threadIdx.x;
    const float* lp = latent + n * ZDIM;
    float a0 = 0.f, a1 = 0.f, a2 = 0.f, a3 = 0.f;
#pragma unroll 4
    for (int z = 0; z < ZDIM; z += 4) {
        a0 = fmaf(lp[z + 0], dense_w[(z + 0) * CINCH + c], a0);
        a1 = fmaf(lp[z + 1], dense_w[(z + 1) * CINCH + c], a1);
        a2 = fmaf(lp[z + 2], dense_w[(z + 2) * CINCH + c], a2);
        a3 = fmaf(lp[z + 3], dense_w[(z + 3) * CINCH + c], a3);
    }
    g_s[n * CINCH + c] = (a0 + a1 + a2 + a3) * DENSE_COEF + dense_b[c];
}

__global__ void k_w2(const float* __restrict__ conv_w) {
    const int i = blockIdx.x * 256 + threadIdx.x;
    float acc = 0.0f;
#pragma unroll
    for (int t = 0; t < 9; ++t) {
        float v = conv_w[t * (CINCH * COUTC) + i];
        acc = fmaf(v, v, acc);
    }
    g_w2[i] = acc * CONV_COEF2;
}

__global__ void k_demod() {
    __shared__ float s2[CINCH];
    const int n = blockIdx.x;
    const int c = threadIdx.x;
    float sv = g_s[n * CINCH + c];
    s2[c] = sv * sv;
    __syncthreads();
    float acc = 0.0f;
#pragma unroll 8
    for (int ci = 0; ci < CINCH; ++ci)
        acc = fmaf(s2[ci], g_w2[ci * COUTC + c], acc);
    g_d[n * COUTC + c] = rsqrtf(acc + 1e-8f);
}

// ---------------------------------------------------------------------------
// Weight transform: U[pos][cout][cin] = (G (w*coef) G^T)[pos], fp16  (R9 exact)
// ---------------------------------------------------------------------------
__global__ void k_wino_u(const float* __restrict__ conv_w) {
    __shared__ float tw[9][32][33];
    const int ci0 = blockIdx.x * 32;
    const int co0 = blockIdx.y * 32;
    const int tx = threadIdx.x;   // 0..31
    const int ty = threadIdx.y;   // 0..7
#pragma unroll
    for (int t = 0; t < 9; ++t)
#pragma unroll
        for (int i = 0; i < 4; ++i) {
            const int ci = ty + i * 8;
            tw[t][ci][tx] = conv_w[((size_t)t * CINCH + ci0 + ci) * COUTC + co0 + tx];
        }
    __syncthreads();
#pragma unroll
    for (int i = 0; i < 4; ++i) {
        const int co_l = ty + i * 8;
        float g[3][3];
#pragma unroll
        for (int k = 0; k < 9; ++k)
            g[k / 3][k % 3] = tw[k][tx][co_l] * CONV_COEF;
        float tg[4][3];
#pragma unroll
        for (int c = 0; c < 3; ++c) {
            tg[0][c] = g[0][c];
            tg[1][c] = 0.5f * (g[0][c] + g[1][c] + g[2][c]);
            tg[2][c] = 0.5f * (g[0][c] - g[1][c] + g[2][c]);
            tg[3][c] = g[2][c];
        }
        const size_t b = (size_t)(co0 + co_l) * CINCH + ci0 + tx;
#pragma unroll
        for (int r = 0; r < 4; ++r) {
            const float u0 = tg[r][0];
            const float u1 = 0.5f * (tg[r][0] + tg[r][1] + tg[r][2]);
            const float u2 = 0.5f * (tg[r][0] - tg[r][1] + tg[r][2]);
            const float u3 = tg[r][2];
            g_U[(size_t)(r * 4 + 0) * (CINCH * COUTC) + b] = __float2half_rn(u0);
            g_U[(size_t)(r * 4 + 1) * (CINCH * COUTC) + b] = __float2half_rn(u1);
            g_U[(size_t)(r * 4 + 2) * (CINCH * COUTC) + b] = __float2half_rn(u2);
            g_U[(size_t)(r * 4 + 3) * (CINCH * COUTC) + b] = __float2half_rn(u3);
        }
    }
}

// ---------------------------------------------------------------------------
// Input transform fused with modulation: V[pos][p][cin] = B^T (x*s) B  (R9 exact)
// ---------------------------------------------------------------------------
__global__ void k_wino_v(const float* __restrict__ data) {
    const int p  = blockIdx.x;
    const int ci = threadIdx.x * 2;
    const int n  = p >> 10;
    const int ty = (p >> 5) & 31;
    const int tx = p & 31;
    const int y0 = 2 * ty - 1;
    const int x0 = 2 * tx - 1;
    const float2 sv = *(const float2*)(g_s + n * CINCH + ci);

    float2 d[4][4];
#pragma unroll
    for (int r = 0; r < 4; ++r) {
        const int h = y0 + r;
        const bool hv = (unsigned)h < 64u;
#pragma unroll
        for (int c = 0; c < 4; ++c) {
            const int w = x0 + c;
            float2 v = make_float2(0.f, 0.f);
            if (hv && (unsigned)w < 64u) {
                const float2 x = *(const float2*)(
                    data + ((size_t)((n * 64 + h) * 64 + w)) * CINCH + ci);
                v.x = x.x * sv.x;
                v.y = x.y * sv.y;
            }
            d[r][c] = v;
        }
    }
    float2 t[4][4];
#pragma unroll
    for (int c = 0; c < 4; ++c) {
        t[0][c] = make_float2(d[0][c].x - d[2][c].x, d[0][c].y - d[2][c].y);
        t[1][c] = make_float2(d[1][c].x + d[2][c].x, d[1][c].y + d[2][c].y);
        t[2][c] = make_float2(d[2][c].x - d[1][c].x, d[2][c].y - d[1][c].y);
        t[3][c] = make_float2(d[1][c].x - d[3][c].x, d[1][c].y - d[3][c].y);
    }
    const size_t pb = (size_t)p * CINCH + ci;
    const size_t ps = (size_t)P_TILES * CINCH;
#pragma unroll
    for (int r = 0; r < 4; ++r) {
        float2 v0 = make_float2(t[r][0].x - t[r][2].x, t[r][0].y - t[r][2].y);
        float2 v1 = make_float2(t[r][1].x + t[r][2].x, t[r][1].y + t[r][2].y);
        float2 v2 = make_float2(t[r][2].x - t[r][1].x, t[r][2].y - t[r][1].y);
        float2 v3 = make_float2(t[r][1].x - t[r][3].x, t[r][1].y - t[r][3].y);
        *(__half2*)(g_V + (size_t)(r * 4 + 0) * ps + pb) = __floats2half2_rn(v0.x, v0.y);
        *(__half2*)(g_V + (size_t)(r * 4 + 1) * ps + pb) = __floats2half2_rn(v1.x, v1.y);
        *(__half2*)(g_V + (size_t)(r * 4 + 2) * ps + pb) = __floats2half2_rn(v2.x, v2.y);
        *(__half2*)(g_V + (size_t)(r * 4 + 3) * ps + pb) = __floats2half2_rn(v3.x, v3.y);
    }
}

// ---------------------------------------------------------------------------
// Staging for the Winograd-domain GEMM (BK=64)  (R9 exact)
// ---------------------------------------------------------------------------
__device__ __forceinline__ void stage_load(uint32_t sA, uint32_t sB, int s,
                                           int tid, int pos, int bm, int bn) {
    const int ci0 = s * BK;
    const __half* va = g_V + (size_t)pos * (P_TILES * CINCH);
    const __half* ub = g_U + (size_t)pos * (CINCH * COUTC);
#pragma unroll
    for (int i = 0; i < 4; ++i) {
        const int c  = tid + 256 * i;
        const int m  = c >> 3;
        const int ch = c & 7;
        cpa16(sA + m * ROWB + ch * 16,
              va + (size_t)(bm + m) * CINCH + ci0 + ch * 8);
    }
#pragma unroll
    for (int i = 0; i < 4; ++i) {
        const int c  = tid + 256 * i;
        const int nn = c >> 3;
        const int ch = c & 7;
        cpa16(sB + nn * ROWB + ch * 16,
              ub + (size_t)(bn + nn) * CINCH + ci0 + ch * 8);
    }
}

// ---------------------------------------------------------------------------
// Winograd-domain GEMM (R9 exact): 128x128 tile, BK=64, 3-stage, 2 CTAs/SM
// ---------------------------------------------------------------------------
__global__ void __launch_bounds__(256, 2)
k_wino_gemm() {
    extern __shared__ char sm[];
    __shared__ int s_tile;
    const uint32_t sbase = smem_u32(sm);

    const int tid  = threadIdx.x;
    const int wid  = tid >> 5;
    const int lane = tid & 31;
    const int gid  = lane >> 2;
    const int tid4 = lane & 3;
    const int l15  = lane & 15;
    const int lhi  = (lane >> 4) & 1;
    const int wm = (wid >> 2) * 64;
    const int wn = (wid & 3) * 32;

    uint32_t sA[STAGES], sB[STAGES];
#pragma unroll
    for (int st = 0; st < STAGES; ++st) {
        sA[st] = sbase + st * STAGE_BYTES;
        sB[st] = sA[st] + A_ST_BYTES;
    }
    const uint32_t a_off = (uint32_t)(wm + l15) * ROWB + lhi * 16;
    const uint32_t b_off = (uint32_t)(wn + l15) * ROWB + lhi * 16;

    for (;;) {
        CP_WAIT0();
        __syncthreads();
        if (tid == 0) s_tile = atomicAdd(&g_ctr, 1);
        __syncthreads();
        const int t = s_tile;
        if (t >= NTILES_G) break;

        const int bn  = (t & 3) * BN;
        const int bm  = ((t >> 2) & 63) * BM;
        const int pos = t >> 8;

        float acc[4][4][4];
#pragma unroll
        for (int i = 0; i < 4; ++i)
#pragma unroll
            for (int j = 0; j < 4; ++j)
#pragma unroll
                for (int r = 0; r < 4; ++r) acc[i][j][r] = 0.0f;

        stage_load(sA[0], sB[0], 0, tid, pos, bm, bn);
        CP_COMMIT();
        stage_load(sA[1], sB[1], 1, tid, pos, bm, bn);
        CP_COMMIT();

        int buf = 0, nbuf = 2;
#pragma unroll 1
        for (int s = 0; s < NSTG; ++s) {
            CP_WAIT1();
            __syncthreads();

            if (s + 2 < NSTG)
                stage_load(sA[nbuf], sB[nbuf], s + 2, tid, pos, bm, bn);
            CP_COMMIT();

            const uint32_t Ab = sA[buf] + a_off;
            const uint32_t Bb = sB[buf] + b_off;

#pragma unroll
            for (int kk = 0; kk < 4; ++kk) {
                uint32_t a[4][4];
#pragma unroll
                for (int i = 0; i < 4; ++i)
                    LDMX4(a[i], Ab + i * (16 * ROWB) + kk * 32);
                uint32_t b[2][4];
#pragma unroll
                for (int j2 = 0; j2 < 2; ++j2)
                    LDMX4(b[j2], Bb + j2 * (16 * ROWB) + kk * 32);

#pragma unroll
                for (int i = 0; i < 4; ++i)
#pragma unroll
                    for (int j = 0; j < 4; ++j) {
                        const int j2 = j >> 1, od = j & 1;
                        MMA_F16(acc[i][j], a[i], b[j2][od], b[j2][2 + od]);
                    }
            }

            buf  = (buf == STAGES - 1) ? 0 : buf + 1;
            nbuf = (nbuf == STAGES - 1) ? 0 : nbuf + 1;
        }

        // write M (fp16, packed half2)
        __half* mb = g_M + (size_t)pos * (P_TILES * COUTC);
#pragma unroll
        for (int j = 0; j < 4; ++j) {
            const int col = bn + wn + j * 8 + 2 * tid4;
#pragma unroll
            for (int i = 0; i < 4; ++i) {
                const int r0 = bm + wm + i * 16 + gid;
#pragma unroll
                for (int half = 0; half < 2; ++half) {
                    const int rr = r0 + half * 8;
                    *(__half2*)(mb + (size_t)rr * COUTC + col) =
                        __floats2half2_rn(acc[i][j][half * 2 + 0],
                                          acc[i][j][half * 2 + 1]);
                }
            }
        }
    }
}

// ---------------------------------------------------------------------------
// Inverse transform + fused epilogue (demod, bias, noise, leaky)  (R9 exact)
// ---------------------------------------------------------------------------
__global__ void k_wino_out(const float* __restrict__ bias,
                           const float* __restrict__ ncoef,
                           const float* __restrict__ noise,
                           float* __restrict__ out) {
    const int p  = blockIdx.x;
    const int co = threadIdx.x * 2;
    const int n  = p >> 10;
    const int ty = (p >> 5) & 31;
    const int tx = p & 31;

    float2 m[4][4];
    const size_t pb = (size_t)p * COUTC + co;
    const size_t ps = (size_t)P_TILES * COUTC;
#pragma unroll
    for (int pos = 0; pos < 16; ++pos)
        m[pos >> 2][pos & 3] = __half22float2(*(const __half2*)(g_M + (size_t)pos * ps + pb));

    float2 t0[4], t1[4];
#pragma unroll
    for (int c = 0; c < 4; ++c) {
        t0[c] = make_float2(m[0][c].x + m[1][c].x + m[2][c].x,
                            m[0][c].y + m[1][c].y + m[2][c].y);
        t1[c] = make_float2(m[1][c].x - m[2][c].x - m[3][c].x,
                            m[1][c].y - m[2][c].y - m[3][c].y);
    }
    float2 y[2][2];
    y[0][0] = make_float2(t0[0].x + t0[1].x + t0[2].x, t0[0].y + t0[1].y + t0[2].y);
    y[0][1] = make_float2(t0[1].x - t0[2].x - t0[3].x, t0[1].y - t0[2].y - t0[3].y);
    y[1][0] = make_float2(t1[0].x + t1[1].x + t1[2].x, t1[0].y + t1[1].y + t1[2].y);
    y[1][1] = make_float2(t1[1].x - t1[2].x - t1[3].x, t1[1].y - t1[2].y - t1[3].y);

    const float2 dv = *(const float2*)(g_d + n * COUTC + co);
    const float2 bv = *(const float2*)(bias + co);
    const float2 cv = *(const float2*)(ncoef + co);
#pragma unroll
    for (int r = 0; r < 2; ++r)
#pragma unroll
        for (int c = 0; c < 2; ++c) {
            const int h = 2 * ty + r;
            const int w = 2 * tx + c;
            const size_t idx = ((size_t)((n * 64 + h) * 64 + w)) * COUTC + co;
            const float2 nz = *(const float2*)(noise + idx);
            float2 o;
            o.x = fmaf(y[r][c].x, dv.x, fmaf(nz.x, cv.x, bv.x));
            o.y = fmaf(y[r][c].y, dv.y, fmaf(nz.y, cv.y, bv.y));
            o.x = (o.x >= 0.f) ? o.x : 0.2f * o.x;
            o.y = (o.y >= 0.f) ? o.y : 0.2f * o.y;
            *(float2*)(out + idx) = o;
        }
}

// ---------------------------------------------------------------------------
// Launch: fork the independent prologue work onto side streams so w2/demod/u
// run concurrently with the 36us k_wino_v. Event edges reproduce the exact
// dependency DAG: style -> {v | (w2->demod) | u} -> gemm -> out.
// ---------------------------------------------------------------------------
extern "C" void kernel_launch(void* const* d_in, const int* in_sizes, int n_in,
                              void* d_out, int out_size) {
    const float* data    = (const float*)d_in[0];
    const float* latent  = (const float*)d_in[1];
    const float* dense_w = (const float*)d_in[2];
    const float* dense_b = (const float*)d_in[3];
    const float* conv_w  = (const float*)d_in[4];
    const float* bias    = (const float*)d_in[5];
    const float* ncoef   = (const float*)d_in[6];
    const float* noise   = (const float*)d_in[7];
    float* out = (float*)d_out;

    static bool init_done = false;
    static cudaStream_t s1, s2;
    static cudaEvent_t eStyle, eS1, eS2;
    if (!init_done) {
        cudaFuncSetAttribute(k_wino_gemm, cudaFuncAttributeMaxDynamicSharedMemorySize,
                             SMEM_TOTAL);
        cudaStreamCreateWithFlags(&s1, cudaStreamNonBlocking);
        cudaStreamCreateWithFlags(&s2, cudaStreamNonBlocking);
        cudaEventCreateWithFlags(&eStyle, cudaEventDisableTiming);
        cudaEventCreateWithFlags(&eS1, cudaEventDisableTiming);
        cudaEventCreateWithFlags(&eS2, cudaEventDisableTiming);
        init_done = true;
    }

    // main stream (0): style, then v (v needs only style)
    k_style<<<NB, CINCH>>>(latent, dense_w, dense_b);
    cudaEventRecord(eStyle, 0);

    // side stream 1: w2 -> demod (demod needs style + w2; eStyle wait covers style)
    cudaStreamWaitEvent(s1, eStyle, 0);
    k_w2<<<(CINCH * COUTC) / 256, 256, 0, s1>>>(conv_w);
    k_demod<<<NB, COUTC, 0, s1>>>();
    cudaEventRecord(eS1, s1);

    // side stream 2: weight transform U (independent of style; wait joins capture)
    cudaStreamWaitEvent(s2, eStyle, 0);
    k_wino_u<<<dim3(CINCH / 32, COUTC / 32), dim3(32, 8), 0, s2>>>(conv_w);
    cudaEventRecord(eS2, s2);

    // main stream: V runs concurrently with s1/s2 work
    k_wino_v<<<P_TILES, 256>>>(data);

    // join: gemm needs V + U; out needs gemm + demod
    cudaStreamWaitEvent(0, eS1, 0);
    cudaStreamWaitEvent(0, eS2, 0);
    k_wino_gemm<<<GRID_P, 256, SMEM_TOTAL>>>();
    k_wino_out<<<P_TILES, 256>>>(bias, ncoef, noise, out);
}

// round 16
// speedup vs baseline: 1.0164x; 1.0164x over previous
#include <cuda_runtime.h>
#include <cuda_fp16.h>
#include <cstdint>

// ---------------------------------------------------------------------------
// Problem constants
// ---------------------------------------------------------------------------
#define NB    8
#define CINCH 512
#define COUTC 512
#define ZDIM  512
#define M_TOT (NB * 64 * 64)        // 32768 pixels
#define P_TILES 8192                // 8 images * 32*32 Winograd tiles (2x2 out)

#define DENSE_COEF (0.0625f)        // sqrt(2/512)
#define CONV_COEF  (1.0f / 48.0f)   // sqrt(2/4608)
#define CONV_COEF2 (1.0f / 2304.0f)

// Winograd-domain GEMM tiling: per pos, [8192 x 512] * [512 x 512]
#define BM 128
#define BN 128
#define BK 64
#define NSTG 8                      // 512 / 64 k-stages per tile
#define STAGES 3
#define NTILES_G (16 * (P_TILES / BM) * (COUTC / BN))   // 4096
#define GRID_P 304                  // persistent CTAs (2 per SM)

// smem rows: 64 halves (128B data) padded to 144B -> conflict-free ldmatrix
// (row r word-offset = 36r mod 32 = 4r -> 8 rows cover all 32 banks disjointly)
#define ROWB 144
#define A_ST_BYTES (BM * ROWB)      // 18432
#define B_ST_BYTES (BN * ROWB)      // 18432
#define STAGE_BYTES (A_ST_BYTES + B_ST_BYTES)   // 36864
#define SMEM_TOTAL (STAGES * STAGE_BYTES)       // 110592

// ---------------------------------------------------------------------------
// Scratch (device globals; no runtime allocation allowed)
// ---------------------------------------------------------------------------
__device__ float  g_s[NB * CINCH];
__device__ float  g_d[NB * COUTC];
__device__ float  g_w2[CINCH * COUTC];
__device__ __half g_V[16 * P_TILES * CINCH];    // input transform  [pos][p][cin]
__device__ __half g_U[16 * CINCH * COUTC];      // weight transform [pos][cout][cin]
__device__ __half g_M[16 * P_TILES * COUTC];    // GEMM out fp16    [pos][p][cout]
__device__ int    g_ctr;                        // persistent tile queue

// ---------------------------------------------------------------------------
// Helpers
// ---------------------------------------------------------------------------
__device__ __forceinline__ uint32_t smem_u32(const void* p) {
    uint32_t a;
    asm("{ .reg .u64 t; cvta.to.shared.u64 t, %1; cvt.u32.u64 %0, t; }" : "=r"(a) : "l"(p));
    return a;
}

__device__ __forceinline__ void cpa16(uint32_t dst, const void* src) {
    asm volatile("cp.async.cg.shared.global.L2::128B [%0], [%1], 16;"
                 :: "r"(dst), "l"(src) : "memory");
}

#define CP_COMMIT() asm volatile("cp.async.commit_group;" ::: "memory")
#define CP_WAIT1()  asm volatile("cp.async.wait_group 1;" ::: "memory")
#define CP_WAIT0()  asm volatile("cp.async.wait_group 0;" ::: "memory")

#define LDMX4(r, addr)                                                        \
    asm volatile("ldmatrix.sync.aligned.m8n8.x4.shared.b16 {%0,%1,%2,%3}, [%4];" \
                 : "=r"((r)[0]), "=r"((r)[1]), "=r"((r)[2]), "=r"((r)[3])     \
                 : "r"(addr))

#define MMA_F16(d, a, b0, b1)                                                 \
    asm volatile(                                                             \
        "mma.sync.aligned.m16n8k16.row.col.f32.f16.f16.f32 "                  \
        "{%0,%1,%2,%3}, {%4,%5,%6,%7}, {%8,%9}, {%0,%1,%2,%3};"               \
        : "+f"((d)[0]), "+f"((d)[1]), "+f"((d)[2]), "+f"((d)[3])              \
        : "r"((a)[0]), "r"((a)[1]), "r"((a)[2]), "r"((a)[3]),                 \
          "r"(b0), "r"(b1))

// ---------------------------------------------------------------------------
// Prologue: style vector, w^2 reduction, demod
// ---------------------------------------------------------------------------
__global__ void k_style(const float* __restrict__ latent,
                        const float* __restrict__ dense_w,
                        const float* __restrict__ dense_b) {
    if (blockIdx.x == 0 && threadIdx.x == 0) g_ctr = 0;   // reset tile queue
    const int n = blockIdx.x;
    const int c = threadIdx.x;
    const float* lp = latent + n * ZDIM;
    float a0 = 0.f, a1 = 0.f, a2 = 0.f, a3 = 0.f;
#pragma unroll 4
    for (int z = 0; z < ZDIM; z += 4) {
        a0 = fmaf(lp[z + 0], dense_w[(z + 0) * CINCH + c], a0);
        a1 = fmaf(lp[z + 1], dense_w[(z + 1) * CINCH + c], a1);
        a2 = fmaf(lp[z + 2], dense_w[(z + 2) * CINCH + c], a2);
        a3 = fmaf(lp[z + 3], dense_w[(z + 3) * CINCH + c], a3);
    }
    g_s[n * CINCH + c] = (a0 + a1 + a2 + a3) * DENSE_COEF + dense_b[c];
}

__global__ void k_w2(const float* __restrict__ conv_w) {
    const int i = blockIdx.x * 256 + threadIdx.x;
    float acc = 0.0f;
#pragma unroll
    for (int t = 0; t < 9; ++t) {
        float v = conv_w[t * (CINCH * COUTC) + i];
        acc = fmaf(v, v, acc);
    }
    g_w2[i] = acc * CONV_COEF2;
}

__global__ void k_demod() {
    __shared__ float s2[CINCH];
    const int n = blockIdx.x;
    const int c = threadIdx.x;
    float sv = g_s[n * CINCH + c];
    s2[c] = sv * sv;
    __syncthreads();
    float acc = 0.0f;
#pragma unroll 8
    for (int ci = 0; ci < CINCH; ++ci)
        acc = fmaf(s2[ci], g_w2[ci * COUTC + c], acc);
    g_d[n * COUTC + c] = rsqrtf(acc + 1e-8f);
}

// ---------------------------------------------------------------------------
// Weight transform: U[pos][cout][cin] = (G (w*coef) G^T)[pos], fp16
// ---------------------------------------------------------------------------
__global__ void k_wino_u(const float* __restrict__ conv_w) {
    __shared__ float tw[9][32][33];
    const int ci0 = blockIdx.x * 32;
    const int co0 = blockIdx.y * 32;
    const int tx = threadIdx.x;   // 0..31
    const int ty = threadIdx.y;   // 0..7
#pragma unroll
    for (int t = 0; t < 9; ++t)
#pragma unroll
        for (int i = 0; i < 4; ++i) {
            const int ci = ty + i * 8;
            tw[t][ci][tx] = conv_w[((size_t)t * CINCH + ci0 + ci) * COUTC + co0 + tx];
        }
    __syncthreads();
#pragma unroll
    for (int i = 0; i < 4; ++i) {
        const int co_l = ty + i * 8;
        float g[3][3];
#pragma unroll
        for (int k = 0; k < 9; ++k)
            g[k / 3][k % 3] = tw[k][tx][co_l] * CONV_COEF;
        float tg[4][3];
#pragma unroll
        for (int c = 0; c < 3; ++c) {
            tg[0][c] = g[0][c];
            tg[1][c] = 0.5f * (g[0][c] + g[1][c] + g[2][c]);
            tg[2][c] = 0.5f * (g[0][c] - g[1][c] + g[2][c]);
            tg[3][c] = g[2][c];
        }
        const size_t b = (size_t)(co0 + co_l) * CINCH + ci0 + tx;
#pragma unroll
        for (int r = 0; r < 4; ++r) {
            const float u0 = tg[r][0];
            const float u1 = 0.5f * (tg[r][0] + tg[r][1] + tg[r][2]);
            const float u2 = 0.5f * (tg[r][0] - tg[r][1] + tg[r][2]);
            const float u3 = tg[r][2];
            g_U[(size_t)(r * 4 + 0) * (CINCH * COUTC) + b] = __float2half_rn(u0);
            g_U[(size_t)(r * 4 + 1) * (CINCH * COUTC) + b] = __float2half_rn(u1);
            g_U[(size_t)(r * 4 + 2) * (CINCH * COUTC) + b] = __float2half_rn(u2);
            g_U[(size_t)(r * 4 + 3) * (CINCH * COUTC) + b] = __float2half_rn(u3);
        }
    }
}

// ---------------------------------------------------------------------------
// Input transform fused with modulation: V[pos][p][cin] = B^T (x*s) B, fp16
// grid = 8192, block = 256 (2 consecutive cin per thread, half2 stores)
// ---------------------------------------------------------------------------
__global__ void k_wino_v(const float* __restrict__ data) {
    const int p  = blockIdx.x;
    const int ci = threadIdx.x * 2;
    const int n  = p >> 10;
    const int ty = (p >> 5) & 31;
    const int tx = p & 31;
    const int y0 = 2 * ty - 1;
    const int x0 = 2 * tx - 1;
    const float2 sv = *(const float2*)(g_s + n * CINCH + ci);

    float2 d[4][4];
#pragma unroll
    for (int r = 0; r < 4; ++r) {
        const int h = y0 + r;
        const bool hv = (unsigned)h < 64u;
#pragma unroll
        for (int c = 0; c < 4; ++c) {
            const int w = x0 + c;
            float2 v = make_float2(0.f, 0.f);
            if (hv && (unsigned)w < 64u) {
                const float2 x = *(const float2*)(
                    data + ((size_t)((n * 64 + h) * 64 + w)) * CINCH + ci);
                v.x = x.x * sv.x;
                v.y = x.y * sv.y;
            }
            d[r][c] = v;
        }
    }
    float2 t[4][4];
#pragma unroll
    for (int c = 0; c < 4; ++c) {
        t[0][c] = make_float2(d[0][c].x - d[2][c].x, d[0][c].y - d[2][c].y);
        t[1][c] = make_float2(d[1][c].x + d[2][c].x, d[1][c].y + d[2][c].y);
        t[2][c] = make_float2(d[2][c].x - d[1][c].x, d[2][c].y - d[1][c].y);
        t[3][c] = make_float2(d[1][c].x - d[3][c].x, d[1][c].y - d[3][c].y);
    }
    const size_t pb = (size_t)p * CINCH + ci;
    const size_t ps = (size_t)P_TILES * CINCH;
#pragma unroll
    for (int r = 0; r < 4; ++r) {
        float2 v0 = make_float2(t[r][0].x - t[r][2].x, t[r][0].y - t[r][2].y);
        float2 v1 = make_float2(t[r][1].x + t[r][2].x, t[r][1].y + t[r][2].y);
        float2 v2 = make_float2(t[r][2].x - t[r][1].x, t[r][2].y - t[r][1].y);
        float2 v3 = make_float2(t[r][1].x - t[r][3].x, t[r][1].y - t[r][3].y);
        *(__half2*)(g_V + (size_t)(r * 4 + 0) * ps + pb) = __floats2half2_rn(v0.x, v0.y);
        *(__half2*)(g_V + (size_t)(r * 4 + 1) * ps + pb) = __floats2half2_rn(v1.x, v1.y);
        *(__half2*)(g_V + (size_t)(r * 4 + 2) * ps + pb) = __floats2half2_rn(v2.x, v2.y);
        *(__half2*)(g_V + (size_t)(r * 4 + 3) * ps + pb) = __floats2half2_rn(v3.x, v3.y);
    }
}

// ---------------------------------------------------------------------------
// Staging for the Winograd-domain GEMM (BK=64: 8 x 16B chunks per row)
// ---------------------------------------------------------------------------
__device__ __forceinline__ void stage_load(uint32_t sA, uint32_t sB, int s,
                                           int tid, int pos, int bm, int bn) {
    const int ci0 = s * BK;
    const __half* va = g_V + (size_t)pos * (P_TILES * CINCH);
    const __half* ub = g_U + (size_t)pos * (CINCH * COUTC);
    // A: 128 rows x 8 chunks of 16B = 1024 chunks / 256 thr = 4 each
#pragma unroll
    for (int i = 0; i < 4; ++i) {
        const int c  = tid + 256 * i;
        const int m  = c >> 3;
        const int ch = c & 7;
        cpa16(sA + m * ROWB + ch * 16,
              va + (size_t)(bm + m) * CINCH + ci0 + ch * 8);
    }
    // B: 128 rows x 8 chunks of 16B
#pragma unroll
    for (int i = 0; i < 4; ++i) {
        const int c  = tid + 256 * i;
        const int nn = c >> 3;
        const int ch = c & 7;
        cpa16(sB + nn * ROWB + ch * 16,
              ub + (size_t)(bn + nn) * CINCH + ci0 + ch * 8);
    }
}

// ---------------------------------------------------------------------------
// Winograd-domain GEMM: 16 x [8192 x 512 x 512], persistent fp16 mma.sync
// grid = 304, block = 256, tile 128x128, BK=64 (8 stages, 3-deep pipeline)
// ---------------------------------------------------------------------------
__global__ void __launch_bounds__(256, 2)
k_wino_gemm() {
    extern __shared__ char sm[];
    __shared__ int s_tile;
    const uint32_t sbase = smem_u32(sm);

    const int tid  = threadIdx.x;
    const int wid  = tid >> 5;
    const int lane = tid & 31;
    const int gid  = lane >> 2;
    const int tid4 = lane & 3;
    const int l15  = lane & 15;
    const int lhi  = (lane >> 4) & 1;
    const int wm = (wid >> 2) * 64;
    const int wn = (wid & 3) * 32;

    uint32_t sA[STAGES], sB[STAGES];
#pragma unroll
    for (int st = 0; st < STAGES; ++st) {
        sA[st] = sbase + st * STAGE_BYTES;
        sB[st] = sA[st] + A_ST_BYTES;
    }
    const uint32_t a_off = (uint32_t)(wm + l15) * ROWB + lhi * 16;
    const uint32_t b_off = (uint32_t)(wn + l15) * ROWB + lhi * 16;

    for (;;) {
        CP_WAIT0();
        __syncthreads();
        if (tid == 0) s_tile = atomicAdd(&g_ctr, 1);
        __syncthreads();
        const int t = s_tile;
        if (t >= NTILES_G) break;

        const int bn  = (t & 3) * BN;
        const int bm  = ((t >> 2) & 63) * BM;
        const int pos = t >> 8;

        float acc[4][4][4];
#pragma unroll
        for (int i = 0; i < 4; ++i)
#pragma unroll
            for (int j = 0; j < 4; ++j)
#pragma unroll
                for (int r = 0; r < 4; ++r) acc[i][j][r] = 0.0f;

        stage_load(sA[0], sB[0], 0, tid, pos, bm, bn);
        CP_COMMIT();
        stage_load(sA[1], sB[1], 1, tid, pos, bm, bn);
        CP_COMMIT();

        int buf = 0, nbuf = 2;
#pragma unroll 1
        for (int s = 0; s < NSTG; ++s) {
            CP_WAIT1();
            __syncthreads();

            if (s + 2 < NSTG)
                stage_load(sA[nbuf], sB[nbuf], s + 2, tid, pos, bm, bn);
            CP_COMMIT();

            const uint32_t Ab = sA[buf] + a_off;
            const uint32_t Bb = sB[buf] + b_off;

#pragma unroll
            for (int kk = 0; kk < 4; ++kk) {
                uint32_t a[4][4];
#pragma unroll
                for (int i = 0; i < 4; ++i)
                    LDMX4(a[i], Ab + i * (16 * ROWB) + kk * 32);
                uint32_t b[2][4];
#pragma unroll
                for (int j2 = 0; j2 < 2; ++j2)
                    LDMX4(b[j2], Bb + j2 * (16 * ROWB) + kk * 32);

#pragma unroll
                for (int i = 0; i < 4; ++i)
#pragma unroll
                    for (int j = 0; j < 4; ++j) {
                        const int j2 = j >> 1, od = j & 1;
                        MMA_F16(acc[i][j], a[i], b[j2][od], b[j2][2 + od]);
                    }
            }

            buf  = (buf == STAGES - 1) ? 0 : buf + 1;
            nbuf = (nbuf == STAGES - 1) ? 0 : nbuf + 1;
        }

        // write M (fp16, packed half2)
        __half* mb = g_M + (size_t)pos * (P_TILES * COUTC);
#pragma unroll
        for (int j = 0; j < 4; ++j) {
            const int col = bn + wn + j * 8 + 2 * tid4;
#pragma unroll
            for (int i = 0; i < 4; ++i) {
                const int r0 = bm + wm + i * 16 + gid;
#pragma unroll
                for (int half = 0; half < 2; ++half) {
                    const int rr = r0 + half * 8;
                    *(__half2*)(mb + (size_t)rr * COUTC + col) =
                        __floats2half2_rn(acc[i][j][half * 2 + 0],
                                          acc[i][j][half * 2 + 1]);
                }
            }
        }
    }
}

// ---------------------------------------------------------------------------
// Inverse transform + fused epilogue (demod, bias, noise, leaky)
// grid = 8192, block = 256 (2 consecutive couts per thread, half2 loads)
// ---------------------------------------------------------------------------
__global__ void k_wino_out(const float* __restrict__ bias,
                           const float* __restrict__ ncoef,
                           const float* __restrict__ noise,
                           float* __restrict__ out) {
    const int p  = blockIdx.x;
    const int co = threadIdx.x * 2;
    const int n  = p >> 10;
    const int ty = (p >> 5) & 31;
    const int tx = p & 31;

    float2 m[4][4];
    const size_t pb = (size_t)p * COUTC + co;
    const size_t ps = (size_t)P_TILES * COUTC;
#pragma unroll
    for (int pos = 0; pos < 16; ++pos)
        m[pos >> 2][pos & 3] = __half22float2(*(const __half2*)(g_M + (size_t)pos * ps + pb));

    float2 t0[4], t1[4];
#pragma unroll
    for (int c = 0; c < 4; ++c) {
        t0[c] = make_float2(m[0][c].x + m[1][c].x + m[2][c].x,
                            m[0][c].y + m[1][c].y + m[2][c].y);
        t1[c] = make_float2(m[1][c].x - m[2][c].x - m[3][c].x,
                            m[1][c].y - m[2][c].y - m[3][c].y);
    }
    float2 y[2][2];
    y[0][0] = make_float2(t0[0].x + t0[1].x + t0[2].x, t0[0].y + t0[1].y + t0[2].y);
    y[0][1] = make_float2(t0[1].x - t0[2].x - t0[3].x, t0[1].y - t0[2].y - t0[3].y);
    y[1][0] = make_float2(t1[0].x + t1[1].x + t1[2].x, t1[0].y + t1[1].y + t1[2].y);
    y[1][1] = make_float2(t1[1].x - t1[2].x - t1[3].x, t1[1].y - t1[2].y - t1[3].y);

    const float2 dv = *(const float2*)(g_d + n * COUTC + co);
    const float2 bv = *(const float2*)(bias + co);
    const float2 cv = *(const float2*)(ncoef + co);
#pragma unroll
    for (int r = 0; r < 2; ++r)
#pragma unroll
        for (int c = 0; c < 2; ++c) {
            const int h = 2 * ty + r;
            const int w = 2 * tx + c;
            const size_t idx = ((size_t)((n * 64 + h) * 64 + w)) * COUTC + co;
            const float2 nz = *(const float2*)(noise + idx);
            float2 o;
            o.x = fmaf(y[r][c].x, dv.x, fmaf(nz.x, cv.x, bv.x));
            o.y = fmaf(y[r][c].y, dv.y, fmaf(nz.y, cv.y, bv.y));
            o.x = (o.x >= 0.f) ? o.x : 0.2f * o.x;
            o.y = (o.y >= 0.f) ? o.y : 0.2f * o.y;
            *(float2*)(out + idx) = o;
        }
}

// ---------------------------------------------------------------------------
// Launch  (R9 exact: single stream, serial DAG)
// ---------------------------------------------------------------------------
extern "C" void kernel_launch(void* const* d_in, const int* in_sizes, int n_in,
                              void* d_out, int out_size) {
    const float* data    = (const float*)d_in[0];
    const float* latent  = (const float*)d_in[1];
    const float* dense_w = (const float*)d_in[2];
    const float* dense_b = (const float*)d_in[3];
    const float* conv_w  = (const float*)d_in[4];
    const float* bias    = (const float*)d_in[5];
    const float* ncoef   = (const float*)d_in[6];
    const float* noise   = (const float*)d_in[7];
    float* out = (float*)d_out;

    static bool attr_set = false;
    if (!attr_set) {
        cudaFuncSetAttribute(k_wino_gemm, cudaFuncAttributeMaxDynamicSharedMemorySize,
                             SMEM_TOTAL);
        attr_set = true;
    }

    k_style<<<NB, CINCH>>>(latent, dense_w, dense_b);
    k_w2<<<(CINCH * COUTC) / 256, 256>>>(conv_w);
    k_demod<<<NB, COUTC>>>();
    k_wino_u<<<dim3(CINCH / 32, COUTC / 32), dim3(32, 8)>>>(conv_w);
    k_wino_v<<<P_TILES, 256>>>(data);
    k_wino_gemm<<<GRID_P, 256, SMEM_TOTAL>>>();
    k_wino_out<<<P_TILES, 256>>>(bias, ncoef, noise, out);
}

// round 17
// speedup vs baseline: 1.0248x; 1.0083x over previous
#include <cuda_runtime.h>
#include <cuda_fp16.h>
#include <cstdint>

// ---------------------------------------------------------------------------
// Problem constants
// ---------------------------------------------------------------------------
#define NB    8
#define CINCH 512
#define COUTC 512
#define ZDIM  512
#define M_TOT (NB * 64 * 64)        // 32768 pixels
#define P_TILES 8192                // 8 images * 32*32 Winograd tiles (2x2 out)

#define DENSE_COEF (0.0625f)        // sqrt(2/512)
#define CONV_COEF  (1.0f / 48.0f)   // sqrt(2/4608)
#define CONV_COEF2 (1.0f / 2304.0f)

// Winograd-domain GEMM tiling: per pos, [8192 x 512] * [512 x 512]
#define BM 128
#define BN 128
#define BK 64
#define NSTG 8                      // 512 / 64 k-stages per tile
#define STAGES 3
#define NTILES_G (16 * (P_TILES / BM) * (COUTC / BN))   // 4096
#define GRID_P 304                  // persistent CTAs (2 per SM)

// smem rows: 64 halves (128B data) padded to 144B -> conflict-free ldmatrix
#define ROWB 144
#define A_ST_BYTES (BM * ROWB)      // 18432
#define B_ST_BYTES (BN * ROWB)      // 18432
#define STAGE_BYTES (A_ST_BYTES + B_ST_BYTES)   // 36864
#define SMEM_TOTAL (STAGES * STAGE_BYTES)       // 110592

// ---------------------------------------------------------------------------
// Scratch (device globals; no runtime allocation allowed)
// ---------------------------------------------------------------------------
__device__ float  g_s[NB * CINCH];
__device__ float  g_d[NB * COUTC];
__device__ float  g_w2[CINCH * COUTC];
__device__ __half g_V[16 * P_TILES * CINCH];    // input transform  [pos][p][cin]
__device__ __half g_U[16 * CINCH * COUTC];      // weight transform [pos][cout][cin]
__device__ __half g_M[16 * P_TILES * COUTC];    // GEMM out fp16    [pos][p][cout]
__device__ int    g_ctr;                        // persistent tile queue

// ---------------------------------------------------------------------------
// Helpers
// ---------------------------------------------------------------------------
__device__ __forceinline__ uint32_t smem_u32(const void* p) {
    uint32_t a;
    asm("{ .reg .u64 t; cvta.to.shared.u64 t, %1; cvt.u32.u64 %0, t; }" : "=r"(a) : "l"(p));
    return a;
}

__device__ __forceinline__ void cpa16(uint32_t dst, const void* src) {
    asm volatile("cp.async.cg.shared.global.L2::128B [%0], [%1], 16;"
                 :: "r"(dst), "l"(src) : "memory");
}

#define CP_COMMIT() asm volatile("cp.async.commit_group;" ::: "memory")
#define CP_WAIT1()  asm volatile("cp.async.wait_group 1;" ::: "memory")
#define CP_WAIT0()  asm volatile("cp.async.wait_group 0;" ::: "memory")

#define LDMX4(r, addr)                                                        \
    asm volatile("ldmatrix.sync.aligned.m8n8.x4.shared.b16 {%0,%1,%2,%3}, [%4];" \
                 : "=r"((r)[0]), "=r"((r)[1]), "=r"((r)[2]), "=r"((r)[3])     \
                 : "r"(addr))

#define MMA_F16(d, a, b0, b1)                                                 \
    asm volatile(                                                             \
        "mma.sync.aligned.m16n8k16.row.col.f32.f16.f16.f32 "                  \
        "{%0,%1,%2,%3}, {%4,%5,%6,%7}, {%8,%9}, {%0,%1,%2,%3};"               \
        : "+f"((d)[0]), "+f"((d)[1]), "+f"((d)[2]), "+f"((d)[3])              \
        : "r"((a)[0]), "r"((a)[1]), "r"((a)[2]), "r"((a)[3]),                 \
          "r"(b0), "r"(b1))

// ---------------------------------------------------------------------------
// Prologue: style vector, w^2 reduction, demod  (R9 exact)
// ---------------------------------------------------------------------------
__global__ void k_style(const float* __restrict__ latent,
                        const float* __restrict__ dense_w,
                        const float* __restrict__ dense_b) {
    if (blockIdx.x == 0 && threadIdx.x == 0) g_ctr = 0;   // reset tile queue
    const int n = blockIdx.x;
    const int c = threadIdx.x;
    const float* lp = latent + n * ZDIM;
    float a0 = 0.f, a1 = 0.f, a2 = 0.f, a3 = 0.f;
#pragma unroll 4
    for (int z = 0; z < ZDIM; z += 4) {
        a0 = fmaf(lp[z + 0], dense_w[(z + 0) * CINCH + c], a0);
        a1 = fmaf(lp[z + 1], dense_w[(z + 1) * CINCH + c], a1);
        a2 = fmaf(lp[z + 2], dense_w[(z + 2) * CINCH + c], a2);
        a3 = fmaf(lp[z + 3], dense_w[(z + 3) * CINCH + c], a3);
    }
    g_s[n * CINCH + c] = (a0 + a1 + a2 + a3) * DENSE_COEF + dense_b[c];
}

__global__ void k_w2(const float* __restrict__ conv_w) {
    const int i = blockIdx.x * 256 + threadIdx.x;
    float acc = 0.0f;
#pragma unroll
    for (int t = 0; t < 9; ++t) {
        float v = conv_w[t * (CINCH * COUTC) + i];
        acc = fmaf(v, v, acc);
    }
    g_w2[i] = acc * CONV_COEF2;
}

__global__ void k_demod() {
    __shared__ float s2[CINCH];
    const int n = blockIdx.x;
    const int c = threadIdx.x;
    float sv = g_s[n * CINCH + c];
    s2[c] = sv * sv;
    __syncthreads();
    float acc = 0.0f;
#pragma unroll 8
    for (int ci = 0; ci < CINCH; ++ci)
        acc = fmaf(s2[ci], g_w2[ci * COUTC + c], acc);
    g_d[n * COUTC + c] = rsqrtf(acc + 1e-8f);
}

// ---------------------------------------------------------------------------
// Weight transform: U[pos][cout][cin] = (G (w*coef) G^T)[pos], fp16  (R9 exact)
// ---------------------------------------------------------------------------
__global__ void k_wino_u(const float* __restrict__ conv_w) {
    __shared__ float tw[9][32][33];
    const int ci0 = blockIdx.x * 32;
    const int co0 = blockIdx.y * 32;
    const int tx = threadIdx.x;   // 0..31
    const int ty = threadIdx.y;   // 0..7
#pragma unroll
    for (int t = 0; t < 9; ++t)
#pragma unroll
        for (int i = 0; i < 4; ++i) {
            const int ci = ty + i * 8;
            tw[t][ci][tx] = conv_w[((size_t)t * CINCH + ci0 + ci) * COUTC + co0 + tx];
        }
    __syncthreads();
#pragma unroll
    for (int i = 0; i < 4; ++i) {
        const int co_l = ty + i * 8;
        float g[3][3];
#pragma unroll
        for (int k = 0; k < 9; ++k)
            g[k / 3][k % 3] = tw[k][tx][co_l] * CONV_COEF;
        float tg[4][3];
#pragma unroll
        for (int c = 0; c < 3; ++c) {
            tg[0][c] = g[0][c];
            tg[1][c] = 0.5f * (g[0][c] + g[1][c] + g[2][c]);
            tg[2][c] = 0.5f * (g[0][c] - g[1][c] + g[2][c]);
            tg[3][c] = g[2][c];
        }
        const size_t b = (size_t)(co0 + co_l) * CINCH + ci0 + tx;
#pragma unroll
        for (int r = 0; r < 4; ++r) {
            const float u0 = tg[r][0];
            const float u1 = 0.5f * (tg[r][0] + tg[r][1] + tg[r][2]);
            const float u2 = 0.5f * (tg[r][0] - tg[r][1] + tg[r][2]);
            const float u3 = tg[r][2];
            g_U[(size_t)(r * 4 + 0) * (CINCH * COUTC) + b] = __float2half_rn(u0);
            g_U[(size_t)(r * 4 + 1) * (CINCH * COUTC) + b] = __float2half_rn(u1);
            g_U[(size_t)(r * 4 + 2) * (CINCH * COUTC) + b] = __float2half_rn(u2);
            g_U[(size_t)(r * 4 + 3) * (CINCH * COUTC) + b] = __float2half_rn(u3);
        }
    }
}

// ---------------------------------------------------------------------------
// Input transform fused with modulation: V[pos][p][cin] = B^T (x*s) B, fp16
// grid = 8192, block = 256. __launch_bounds__(256, 6): cap regs at 42 so 6
// blocks/SM fit (75% occ vs 52.7% measured) to cover the scattered-load latency.
// ---------------------------------------------------------------------------
__global__ void __launch_bounds__(256, 6)
k_wino_v(const float* __restrict__ data) {
    const int p  = blockIdx.x;
    const int ci = threadIdx.x * 2;
    const int n  = p >> 10;
    const int ty = (p >> 5) & 31;
    const int tx = p & 31;
    const int y0 = 2 * ty - 1;
    const int x0 = 2 * tx - 1;
    const float2 sv = *(const float2*)(g_s + n * CINCH + ci);

    float2 d[4][4];
#pragma unroll
    for (int r = 0; r < 4; ++r) {
        const int h = y0 + r;
        const bool hv = (unsigned)h < 64u;
#pragma unroll
        for (int c = 0; c < 4; ++c) {
            const int w = x0 + c;
            float2 v = make_float2(0.f, 0.f);
            if (hv && (unsigned)w < 64u) {
                const float2 x = *(const float2*)(
                    data + ((size_t)((n * 64 + h) * 64 + w)) * CINCH + ci);
                v.x = x.x * sv.x;
                v.y = x.y * sv.y;
            }
            d[r][c] = v;
        }
    }
    float2 t[4][4];
#pragma unroll
    for (int c = 0; c < 4; ++c) {
        t[0][c] = make_float2(d[0][c].x - d[2][c].x, d[0][c].y - d[2][c].y);
        t[1][c] = make_float2(d[1][c].x + d[2][c].x, d[1][c].y + d[2][c].y);
        t[2][c] = make_float2(d[2][c].x - d[1][c].x, d[2][c].y - d[1][c].y);
        t[3][c] = make_float2(d[1][c].x - d[3][c].x, d[1][c].y - d[3][c].y);
    }
    const size_t pb = (size_t)p * CINCH + ci;
    const size_t ps = (size_t)P_TILES * CINCH;
#pragma unroll
    for (int r = 0; r < 4; ++r) {
        float2 v0 = make_float2(t[r][0].x - t[r][2].x, t[r][0].y - t[r][2].y);
        float2 v1 = make_float2(t[r][1].x + t[r][2].x, t[r][1].y + t[r][2].y);
        float2 v2 = make_float2(t[r][2].x - t[r][1].x, t[r][2].y - t[r][1].y);
        float2 v3 = make_float2(t[r][1].x - t[r][3].x, t[r][1].y - t[r][3].y);
        *(__half2*)(g_V + (size_t)(r * 4 + 0) * ps + pb) = __floats2half2_rn(v0.x, v0.y);
        *(__half2*)(g_V + (size_t)(r * 4 + 1) * ps + pb) = __floats2half2_rn(v1.x, v1.y);
        *(__half2*)(g_V + (size_t)(r * 4 + 2) * ps + pb) = __floats2half2_rn(v2.x, v2.y);
        *(__half2*)(g_V + (size_t)(r * 4 + 3) * ps + pb) = __floats2half2_rn(v3.x, v3.y);
    }
}

// ---------------------------------------------------------------------------
// Staging for the Winograd-domain GEMM (BK=64)  (R9 exact)
// ---------------------------------------------------------------------------
__device__ __forceinline__ void stage_load(uint32_t sA, uint32_t sB, int s,
                                           int tid, int pos, int bm, int bn) {
    const int ci0 = s * BK;
    const __half* va = g_V + (size_t)pos * (P_TILES * CINCH);
    const __half* ub = g_U + (size_t)pos * (CINCH * COUTC);
#pragma unroll
    for (int i = 0; i < 4; ++i) {
        const int c  = tid + 256 * i;
        const int m  = c >> 3;
        const int ch = c & 7;
        cpa16(sA + m * ROWB + ch * 16,
              va + (size_t)(bm + m) * CINCH + ci0 + ch * 8);
    }
#pragma unroll
    for (int i = 0; i < 4; ++i) {
        const int c  = tid + 256 * i;
        const int nn = c >> 3;
        const int ch = c & 7;
        cpa16(sB + nn * ROWB + ch * 16,
              ub + (size_t)(bn + nn) * CINCH + ci0 + ch * 8);
    }
}

// ---------------------------------------------------------------------------
// Winograd-domain GEMM (R9 exact): 128x128 tile, BK=64, 3-stage, 2 CTAs/SM
// ---------------------------------------------------------------------------
__global__ void __launch_bounds__(256, 2)
k_wino_gemm() {
    extern __shared__ char sm[];
    __shared__ int s_tile;
    const uint32_t sbase = smem_u32(sm);

    const int tid  = threadIdx.x;
    const int wid  = tid >> 5;
    const int lane = tid & 31;
    const int gid  = lane >> 2;
    const int tid4 = lane & 3;
    const int l15  = lane & 15;
    const int lhi  = (lane >> 4) & 1;
    const int wm = (wid >> 2) * 64;
    const int wn = (wid & 3) * 32;

    uint32_t sA[STAGES], sB[STAGES];
#pragma unroll
    for (int st = 0; st < STAGES; ++st) {
        sA[st] = sbase + st * STAGE_BYTES;
        sB[st] = sA[st] + A_ST_BYTES;
    }
    const uint32_t a_off = (uint32_t)(wm + l15) * ROWB + lhi * 16;
    const uint32_t b_off = (uint32_t)(wn + l15) * ROWB + lhi * 16;

    for (;;) {
        CP_WAIT0();
        __syncthreads();
        if (tid == 0) s_tile = atomicAdd(&g_ctr, 1);
        __syncthreads();
        const int t = s_tile;
        if (t >= NTILES_G) break;

        const int bn  = (t & 3) * BN;
        const int bm  = ((t >> 2) & 63) * BM;
        const int pos = t >> 8;

        float acc[4][4][4];
#pragma unroll
        for (int i = 0; i < 4; ++i)
#pragma unroll
            for (int j = 0; j < 4; ++j)
#pragma unroll
                for (int r = 0; r < 4; ++r) acc[i][j][r] = 0.0f;

        stage_load(sA[0], sB[0], 0, tid, pos, bm, bn);
        CP_COMMIT();
        stage_load(sA[1], sB[1], 1, tid, pos, bm, bn);
        CP_COMMIT();

        int buf = 0, nbuf = 2;
#pragma unroll 1
        for (int s = 0; s < NSTG; ++s) {
            CP_WAIT1();
            __syncthreads();

            if (s + 2 < NSTG)
                stage_load(sA[nbuf], sB[nbuf], s + 2, tid, pos, bm, bn);
            CP_COMMIT();

            const uint32_t Ab = sA[buf] + a_off;
            const uint32_t Bb = sB[buf] + b_off;

#pragma unroll
            for (int kk = 0; kk < 4; ++kk) {
                uint32_t a[4][4];
#pragma unroll
                for (int i = 0; i < 4; ++i)
                    LDMX4(a[i], Ab + i * (16 * ROWB) + kk * 32);
                uint32_t b[2][4];
#pragma unroll
                for (int j2 = 0; j2 < 2; ++j2)
                    LDMX4(b[j2], Bb + j2 * (16 * ROWB) + kk * 32);

#pragma unroll
                for (int i = 0; i < 4; ++i)
#pragma unroll
                    for (int j = 0; j < 4; ++j) {
                        const int j2 = j >> 1, od = j & 1;
                        MMA_F16(acc[i][j], a[i], b[j2][od], b[j2][2 + od]);
                    }
            }

            buf  = (buf == STAGES - 1) ? 0 : buf + 1;
            nbuf = (nbuf == STAGES - 1) ? 0 : nbuf + 1;
        }

        // write M (fp16, packed half2)
        __half* mb = g_M + (size_t)pos * (P_TILES * COUTC);
#pragma unroll
        for (int j = 0; j < 4; ++j) {
            const int col = bn + wn + j * 8 + 2 * tid4;
#pragma unroll
            for (int i = 0; i < 4; ++i) {
                const int r0 = bm + wm + i * 16 + gid;
#pragma unroll
                for (int half = 0; half < 2; ++half) {
                    const int rr = r0 + half * 8;
                    *(__half2*)(mb + (size_t)rr * COUTC + col) =
                        __floats2half2_rn(acc[i][j][half * 2 + 0],
                                          acc[i][j][half * 2 + 1]);
                }
            }
        }
    }
}

// ---------------------------------------------------------------------------
// Inverse transform + fused epilogue (demod, bias, noise, leaky)  (R9 exact)
// ---------------------------------------------------------------------------
__global__ void k_wino_out(const float* __restrict__ bias,
                           const float* __restrict__ ncoef,
                           const float* __restrict__ noise,
                           float* __restrict__ out) {
    const int p  = blockIdx.x;
    const int co = threadIdx.x * 2;
    const int n  = p >> 10;
    const int ty = (p >> 5) & 31;
    const int tx = p & 31;

    float2 m[4][4];
    const size_t pb = (size_t)p * COUTC + co;
    const size_t ps = (size_t)P_TILES * COUTC;
#pragma unroll
    for (int pos = 0; pos < 16; ++pos)
        m[pos >> 2][pos & 3] = __half22float2(*(const __half2*)(g_M + (size_t)pos * ps + pb));

    float2 t0[4], t1[4];
#pragma unroll
    for (int c = 0; c < 4; ++c) {
        t0[c] = make_float2(m[0][c].x + m[1][c].x + m[2][c].x,
                            m[0][c].y + m[1][c].y + m[2][c].y);
        t1[c] = make_float2(m[1][c].x - m[2][c].x - m[3][c].x,
                            m[1][c].y - m[2][c].y - m[3][c].y);
    }
    float2 y[2][2];
    y[0][0] = make_float2(t0[0].x + t0[1].x + t0[2].x, t0[0].y + t0[1].y + t0[2].y);
    y[0][1] = make_float2(t0[1].x - t0[2].x - t0[3].x, t0[1].y - t0[2].y - t0[3].y);
    y[1][0] = make_float2(t1[0].x + t1[1].x + t1[2].x, t1[0].y + t1[1].y + t1[2].y);
    y[1][1] = make_float2(t1[1].x - t1[2].x - t1[3].x, t1[1].y - t1[2].y - t1[3].y);

    const float2 dv = *(const float2*)(g_d + n * COUTC + co);
    const float2 bv = *(const float2*)(bias + co);
    const float2 cv = *(const float2*)(ncoef + co);
#pragma unroll
    for (int r = 0; r < 2; ++r)
#pragma unroll
        for (int c = 0; c < 2; ++c) {
            const int h = 2 * ty + r;
            const int w = 2 * tx + c;
            const size_t idx = ((size_t)((n * 64 + h) * 64 + w)) * COUTC + co;
            const float2 nz = *(const float2*)(noise + idx);
            float2 o;
            o.x = fmaf(y[r][c].x, dv.x, fmaf(nz.x, cv.x, bv.x));
            o.y = fmaf(y[r][c].y, dv.y, fmaf(nz.y, cv.y, bv.y));
            o.x = (o.x >= 0.f) ? o.x : 0.2f * o.x;
            o.y = (o.y >= 0.f) ? o.y : 0.2f * o.y;
            *(float2*)(out + idx) = o;
        }
}

// ---------------------------------------------------------------------------
// Launch  (R9 exact: single stream, serial DAG)
// ---------------------------------------------------------------------------
extern "C" void kernel_launch(void* const* d_in, const int* in_sizes, int n_in,
                              void* d_out, int out_size) {
    const float* data    = (const float*)d_in[0];
    const float* latent  = (const float*)d_in[1];
    const float* dense_w = (const float*)d_in[2];
    const float* dense_b = (const float*)d_in[3];
    const float* conv_w  = (const float*)d_in[4];
    const float* bias    = (const float*)d_in[5];
    const float* ncoef   = (const float*)d_in[6];
    const float* noise   = (const float*)d_in[7];
    float* out = (float*)d_out;

    static bool attr_set = false;
    if (!attr_set) {
        cudaFuncSetAttribute(k_wino_gemm, cudaFuncAttributeMaxDynamicSharedMemorySize,
                             SMEM_TOTAL);
        attr_set = true;
    }

    k_style<<<NB, CINCH>>>(latent, dense_w, dense_b);
    k_w2<<<(CINCH * COUTC) / 256, 256>>>(conv_w);
    k_demod<<<NB, COUTC>>>();
    k_wino_u<<<dim3(CINCH / 32, COUTC / 32), dim3(32, 8)>>>(conv_w);
    k_wino_v<<<P_TILES, 256>>>(data);
    k_wino_gemm<<<GRID_P, 256, SMEM_TOTAL>>>();
    k_wino_out<<<P_TILES, 256>>>(bias, ncoef, noise, out);
}